// round 2
// baseline (speedup 1.0000x reference)
#include <cuda_runtime.h>
#include <cstdint>
#include <math.h>

#define BB 512
#define TT 255
#define DD 128
#define HH 1024
#define GG 4096   // 4*H
#define KC 1152   // D + H

// ---------------- scratch (device globals: no allocation allowed) ----------
__device__ __align__(16) float g_a[BB * DD];                    // attention weights
__device__ __align__(16) float g_hbuf[2][BB * HH];              // h ping-pong
__device__ __align__(16) float g_c[BB * HH];                    // c state
__device__ __align__(16) float g_wcat[(size_t)GG * KC];         // permuted [W_ih|W_hh], tf32
__device__ __align__(16) float g_bias[GG];                      // permuted b_ih+b_hh

__device__ __forceinline__ float to_tf32(float x) {
    uint32_t u;
    asm("cvt.rna.tf32.f32 %0, %1;" : "=r"(u) : "f"(x));
    return __uint_as_float(u);
}

__device__ __forceinline__ void cp16(float* smem_dst, const float* gmem_src) {
    uint32_t s = (uint32_t)__cvta_generic_to_shared(smem_dst);
    asm volatile("cp.async.cg.shared.global [%0], [%1], 16;\n" :: "r"(s), "l"(gmem_src));
}
__device__ __forceinline__ void cp_commit() {
    asm volatile("cp.async.commit_group;\n");
}
template <int N>
__device__ __forceinline__ void cp_wait() {
    asm volatile("cp.async.wait_group %0;\n" :: "n"(N));
}

// ---------------- kernel 1: e_x + softmax -> g_a ---------------------------
__global__ void attn_kernel(const float* __restrict__ x, const float* __restrict__ wattn) {
    int b = blockIdx.x, d = threadIdx.x;  // 128 threads
    __shared__ float swx[TT];
    __shared__ float red[8];
    for (int i = d; i < TT; i += DD) swx[i] = wattn[2 * HH + i];
    __syncthreads();
    const float* xb = x + (size_t)b * TT * DD + d;
    float e = 0.f;
#pragma unroll 5
    for (int t = 0; t < TT; t++) e += xb[(size_t)t * DD] * swx[t];

    int lane = d & 31, warp = d >> 5;
    float m = e;
#pragma unroll
    for (int o = 16; o; o >>= 1) m = fmaxf(m, __shfl_xor_sync(0xffffffffu, m, o));
    if (!lane) red[warp] = m;
    __syncthreads();
    m = fmaxf(fmaxf(red[0], red[1]), fmaxf(red[2], red[3]));
    float ex = expf(e - m);
    float s = ex;
#pragma unroll
    for (int o = 16; o; o >>= 1) s += __shfl_xor_sync(0xffffffffu, s, o);
    if (!lane) red[4 + warp] = s;
    __syncthreads();
    s = red[4] + red[5] + red[6] + red[7];
    g_a[b * DD + d] = ex / s;
}

// ---------------- kernel 2: w = a * x -> output region 1 -------------------
__global__ void weight_kernel(const float* __restrict__ x, float* __restrict__ outw) {
    size_t n4 = (size_t)BB * TT * DD / 4;
    const float4* x4 = (const float4*)x;
    const float4* a4 = (const float4*)g_a;
    float4* o4 = (float4*)outw;
    for (size_t i = (size_t)blockIdx.x * blockDim.x + threadIdx.x; i < n4;
         i += (size_t)gridDim.x * blockDim.x) {
        size_t b = i / (TT * 32);
        int d4 = (int)(i % 32);
        float4 av = a4[b * 32 + d4];
        float4 xv = x4[i];
        float4 w;
        w.x = av.x * xv.x; w.y = av.y * xv.y; w.z = av.z * xv.z; w.w = av.w * xv.w;
        o4[i] = w;
    }
}

// ---------------- kernel 3: permuted concat weights + bias ------------------
// output column n  <->  original gate row r = (n&3)*1024 + (n>>2)
// so a 128-wide N tile holds 32 complete (i,f,g,o) quadruples.
__global__ void prep_kernel(const float* __restrict__ wih, const float* __restrict__ whh,
                            const float* __restrict__ bih, const float* __restrict__ bhh) {
    size_t n = (size_t)GG * KC;
    size_t tid0 = (size_t)blockIdx.x * blockDim.x + threadIdx.x;
    for (size_t i = tid0; i < n; i += (size_t)gridDim.x * blockDim.x) {
        int k = (int)(i % KC);
        int nn = (int)(i / KC);
        int r = (nn & 3) * HH + (nn >> 2);
        float v = (k < DD) ? wih[(size_t)r * DD + k] : whh[(size_t)r * HH + (k - DD)];
        g_wcat[i] = to_tf32(v);
    }
    if (tid0 < GG) {
        int r = ((int)tid0 & 3) * HH + ((int)tid0 >> 2);
        g_bias[tid0] = bih[r] + bhh[r];
    }
}

// ---------------- kernel 4: zero h0, c0 -------------------------------------
__global__ void zero_kernel() {
    int i = blockIdx.x * blockDim.x + threadIdx.x;
    if (i < BB * HH) { g_hbuf[0][i] = 0.f; g_c[i] = 0.f; }
}

// ---------------- kernel 5: fused GEMM + LSTM step --------------------------
// gates[512,4096] = [w_t | h_{t-1}] (512,1152) @ wcat^T, then pointwise update
// in epilogue. h ping-pong so epilogue writes never race other blocks' loads.
#define SMEM_TILE (128 * 36)
__global__ __launch_bounds__(256) void fused_step(const float* __restrict__ outw,
                                                  float* __restrict__ outh, int t) {
    extern __shared__ float sm[];
    float* As = sm;                        // [2][128][36]
    float* Bs = sm + 2 * SMEM_TILE;        // [2][128][36]

    const float* hin = g_hbuf[t & 1];
    float* hout = g_hbuf[(t + 1) & 1];

    int tid = threadIdx.x;
    int warp = tid >> 5, lane = tid & 31;
    int wm = warp & 1, wn = warp >> 1;     // 2 warps M x 4 warps N
    int bm0 = blockIdx.y * 128, bn0 = blockIdx.x * 128;

    float acc[4][4][4];
#pragma unroll
    for (int i = 0; i < 4; i++)
#pragma unroll
        for (int j = 0; j < 4; j++)
#pragma unroll
            for (int r = 0; r < 4; r++) acc[i][j][r] = 0.f;

    int lr = tid >> 3;          // 0..31
    int lc = (tid & 7) << 2;    // 0,4,...,28

    auto load_tile = [&](int kt, int buf) {
        int ks = kt * 32;
        float* a = As + buf * SMEM_TILE;
        float* b = Bs + buf * SMEM_TILE;
#pragma unroll
        for (int p = 0; p < 4; p++) {
            int m = lr + p * 32;
            const float* srcA;
            if (ks < DD) srcA = outw + ((size_t)(bm0 + m) * TT + t) * DD + ks + lc;
            else         srcA = hin + (size_t)(bm0 + m) * HH + (ks - DD) + lc;
            cp16(a + m * 36 + lc, srcA);
            cp16(b + m * 36 + lc, g_wcat + (size_t)(bn0 + m) * KC + ks + lc);
        }
    };

    load_tile(0, 0);
    cp_commit();

    const int NKT = KC / 32;  // 36
    for (int kt = 0; kt < NKT; kt++) {
        int cur = kt & 1;
        if (kt + 1 < NKT) { load_tile(kt + 1, cur ^ 1); cp_commit(); }
        if (kt + 1 < NKT) cp_wait<1>(); else cp_wait<0>();
        __syncthreads();

        const float* a = As + cur * SMEM_TILE;
        const float* b = Bs + cur * SMEM_TILE;
#pragma unroll
        for (int kk = 0; kk < 32; kk += 8) {
            uint32_t af[4][4], bf[4][2];
#pragma unroll
            for (int mt = 0; mt < 4; mt++) {
                int r0 = wm * 64 + mt * 16 + (lane >> 2);
                int c0 = kk + (lane & 3);
                af[mt][0] = __float_as_uint(a[r0 * 36 + c0]);
                af[mt][1] = __float_as_uint(a[(r0 + 8) * 36 + c0]);
                af[mt][2] = __float_as_uint(a[r0 * 36 + c0 + 4]);
                af[mt][3] = __float_as_uint(a[(r0 + 8) * 36 + c0 + 4]);
            }
#pragma unroll
            for (int nt = 0; nt < 4; nt++) {
                int n0 = wn * 32 + nt * 8 + (lane >> 2);
                int c0 = kk + (lane & 3);
                bf[nt][0] = __float_as_uint(b[n0 * 36 + c0]);
                bf[nt][1] = __float_as_uint(b[n0 * 36 + c0 + 4]);
            }
#pragma unroll
            for (int mt = 0; mt < 4; mt++)
#pragma unroll
                for (int nt = 0; nt < 4; nt++)
                    asm volatile(
                        "mma.sync.aligned.m16n8k8.row.col.f32.tf32.tf32.f32 "
                        "{%0,%1,%2,%3}, {%4,%5,%6,%7}, {%8,%9}, {%0,%1,%2,%3};"
                        : "+f"(acc[mt][nt][0]), "+f"(acc[mt][nt][1]),
                          "+f"(acc[mt][nt][2]), "+f"(acc[mt][nt][3])
                        : "r"(af[mt][0]), "r"(af[mt][1]), "r"(af[mt][2]), "r"(af[mt][3]),
                          "r"(bf[nt][0]), "r"(bf[nt][1]));
        }
        __syncthreads();
    }

    // ---- fused LSTM epilogue ----
    // add (permuted) bias: col depends on nt + lane only
#pragma unroll
    for (int nt = 0; nt < 4; nt++) {
        int cb = bn0 + wn * 32 + nt * 8 + ((lane & 3) << 1);
        float b0 = g_bias[cb], b1 = g_bias[cb + 1];
#pragma unroll
        for (int mt = 0; mt < 4; mt++) {
            acc[mt][nt][0] += b0; acc[mt][nt][1] += b1;
            acc[mt][nt][2] += b0; acc[mt][nt][3] += b1;
        }
    }

    // quadruple exchange: lanes (q, q^1) swap so each thread owns one full
    // (i,f,g,o) quad: even lane -> row r, odd lane -> row r+8.
    bool odd = lane & 1;
    int row_lo = bm0 + wm * 64 + (lane >> 2) + (odd ? 8 : 0);
    int jbase = (bn0 + wn * 32 + ((lane & 2) ? 4 : 0)) >> 2;

#pragma unroll
    for (int mt = 0; mt < 4; mt++) {
        int row = row_lo + mt * 16;
#pragma unroll
        for (int nt = 0; nt < 4; nt++) {
            float v0 = acc[mt][nt][0], v1 = acc[mt][nt][1];
            float v2 = acc[mt][nt][2], v3 = acc[mt][nt][3];
            float w0 = __shfl_xor_sync(0xffffffffu, v0, 1);
            float w1 = __shfl_xor_sync(0xffffffffu, v1, 1);
            float w2 = __shfl_xor_sync(0xffffffffu, v2, 1);
            float w3 = __shfl_xor_sync(0xffffffffu, v3, 1);
            float gi, gf, gg, go;
            if (odd) { gi = w2; gf = w3; gg = v2; go = v3; }
            else     { gi = v0; gf = v1; gg = w0; go = w1; }
            int j = jbase + nt * 2;
            size_t idx = (size_t)row * HH + j;
            float c = g_c[idx];
            float si = 1.f / (1.f + expf(-gi));
            float sf = 1.f / (1.f + expf(-gf));
            float so = 1.f / (1.f + expf(-go));
            float cn = sf * c + si * tanhf(gg);
            float hn = so * tanhf(cn);
            g_c[idx] = cn;
            hout[idx] = hn;
            outh[((size_t)row * TT + t) * HH + j] = hn;
        }
    }
}

// ---------------- launch ----------------------------------------------------
extern "C" void kernel_launch(void* const* d_in, const int* in_sizes, int n_in,
                              void* d_out, int out_size) {
    (void)in_sizes; (void)n_in; (void)out_size;
    const float* x     = (const float*)d_in[0];
    const float* wattn = (const float*)d_in[1];
    // d_in[2] = b_attn: provably irrelevant (softmax shift invariance)
    const float* wih   = (const float*)d_in[3];
    const float* whh   = (const float*)d_in[4];
    const float* bih   = (const float*)d_in[5];
    const float* bhh   = (const float*)d_in[6];

    float* out  = (float*)d_out;
    float* outw = out;                               // (B, T, D)
    float* outh = out + (size_t)BB * TT * DD;        // (B, T, H)

    static const int smem_bytes = 4 * SMEM_TILE * (int)sizeof(float);  // 73728
    cudaFuncSetAttribute(fused_step, cudaFuncAttributeMaxDynamicSharedMemorySize, smem_bytes);

    attn_kernel<<<BB, DD>>>(x, wattn);
    weight_kernel<<<2048, 256>>>(x, outw);
    prep_kernel<<<2048, 256>>>(wih, whh, bih, bhh);
    zero_kernel<<<(BB * HH + 255) / 256, 256>>>();

    dim3 gemm_grid(32, 4);  // N/128 x M/128
    for (int t = 0; t < TT; t++) {
        fused_step<<<gemm_grid, 256, smem_bytes>>>(outw, outh, t);
    }
}

// round 4
// speedup vs baseline: 2.2197x; 2.2197x over previous
#include <cuda_runtime.h>
#include <cuda_fp16.h>
#include <cstdint>
#include <math.h>

#define BB 512
#define TT 255
#define DD 128
#define HH 1024
#define GG 4096   // 4*H
#define KC 1152   // D + H
#define NKT 36    // KC/32

// ---------------- scratch (device globals: no allocation allowed) ----------
__device__ __align__(16) float  g_a[BB * DD];                   // attention weights
__device__ __align__(16) __half g_wh[(size_t)BB * TT * DD];     // w = a*x, fp16 shadow
__device__ __align__(16) __half g_hbuf[2][BB * HH];             // h ping-pong (fp16)
__device__ __align__(16) float  g_c[BB * HH];                   // c state (fp32)
__device__ __align__(16) __half g_wcat[(size_t)GG * KC];        // permuted [W_ih|W_hh] fp16
__device__ __align__(16) float  g_bias[GG];                     // permuted b_ih+b_hh

// smem geometry: rows of 32 halves padded to 40 (80 B) -> conflict-free frag loads
#define ROW_H 40
#define TILE_HALVES (128 * ROW_H)                 // 5120 halves = 10240 B per matrix
#define STAGE_BYTES (2 * TILE_HALVES * 2)         // A + B = 20480 B
#define EPI_STRIDE 132                            // fp32 gate staging stride
#define SMEM_BYTES (128 * EPI_STRIDE * 4)         // 67584 >= 2*STAGE_BYTES (40960)

__device__ __forceinline__ uint32_t smem_u32(const void* p) {
    uint32_t a;
    asm("{ .reg .u64 t; cvta.to.shared.u64 t, %1; cvt.u32.u64 %0, t; }" : "=r"(a) : "l"(p));
    return a;
}
__device__ __forceinline__ void cp16(uint32_t smem_dst, const void* gmem_src) {
    asm volatile("cp.async.cg.shared.global [%0], [%1], 16;\n" :: "r"(smem_dst), "l"(gmem_src));
}
__device__ __forceinline__ void cp_commit() { asm volatile("cp.async.commit_group;\n"); }
template <int N> __device__ __forceinline__ void cp_wait() {
    asm volatile("cp.async.wait_group %0;\n" :: "n"(N));
}
__device__ __forceinline__ float tanh_fast(float x) {
    float y;
    asm("tanh.approx.f32 %0, %1;" : "=f"(y) : "f"(x));
    return y;
}
__device__ __forceinline__ float sigmoid_fast(float x) {
    return __fdividef(1.f, 1.f + __expf(-x));
}

// ---------------- kernel 1: e_x + softmax -> g_a ---------------------------
__global__ void attn_kernel(const float* __restrict__ x, const float* __restrict__ wattn) {
    int b = blockIdx.x, d = threadIdx.x;  // 128 threads
    __shared__ float swx[TT];
    __shared__ float red[8];
    for (int i = d; i < TT; i += DD) swx[i] = wattn[2 * HH + i];
    __syncthreads();
    const float* xb = x + (size_t)b * TT * DD + d;
    float e = 0.f;
#pragma unroll 5
    for (int t = 0; t < TT; t++) e += xb[(size_t)t * DD] * swx[t];
    int lane = d & 31, warp = d >> 5;
    float m = e;
#pragma unroll
    for (int o = 16; o; o >>= 1) m = fmaxf(m, __shfl_xor_sync(0xffffffffu, m, o));
    if (!lane) red[warp] = m;
    __syncthreads();
    m = fmaxf(fmaxf(red[0], red[1]), fmaxf(red[2], red[3]));
    float ex = expf(e - m);
    float s = ex;
#pragma unroll
    for (int o = 16; o; o >>= 1) s += __shfl_xor_sync(0xffffffffu, s, o);
    if (!lane) red[4 + warp] = s;
    __syncthreads();
    s = red[4] + red[5] + red[6] + red[7];
    g_a[b * DD + d] = ex / s;
}

// ---------------- kernel 2: w = a*x -> outw (fp32) + g_wh (fp16) -----------
__global__ void weight_kernel(const float* __restrict__ x, float* __restrict__ outw) {
    size_t n4 = (size_t)BB * TT * DD / 4;
    const float4* x4 = (const float4*)x;
    const float4* a4 = (const float4*)g_a;
    float4* o4 = (float4*)outw;
    __half2* h2 = (__half2*)g_wh;
    for (size_t i = (size_t)blockIdx.x * blockDim.x + threadIdx.x; i < n4;
         i += (size_t)gridDim.x * blockDim.x) {
        size_t b = i / (TT * 32);
        int d4 = (int)(i % 32);
        float4 av = a4[b * 32 + d4];
        float4 xv = x4[i];
        float4 w = make_float4(av.x * xv.x, av.y * xv.y, av.z * xv.z, av.w * xv.w);
        o4[i] = w;
        h2[2 * i]     = __floats2half2_rn(w.x, w.y);
        h2[2 * i + 1] = __floats2half2_rn(w.z, w.w);
    }
}

// ---------------- kernel 3: permuted fp16 weights + bias --------------------
// output col n <-> original gate row r = (n&3)*H + (n>>2): each 4-col group is
// one complete (i,f,g,o) quadruple for unit n>>2.
__global__ void prep_kernel(const float* __restrict__ wih, const float* __restrict__ whh,
                            const float* __restrict__ bih, const float* __restrict__ bhh) {
    size_t n = (size_t)GG * KC;
    size_t tid0 = (size_t)blockIdx.x * blockDim.x + threadIdx.x;
    for (size_t i = tid0; i < n; i += (size_t)gridDim.x * blockDim.x) {
        int k = (int)(i % KC);
        int nn = (int)(i / KC);
        int r = (nn & 3) * HH + (nn >> 2);
        float v = (k < DD) ? wih[(size_t)r * DD + k] : whh[(size_t)r * HH + (k - DD)];
        g_wcat[i] = __float2half_rn(v);
    }
    if (tid0 < GG) {
        int r = ((int)tid0 & 3) * HH + ((int)tid0 >> 2);
        g_bias[tid0] = bih[r] + bhh[r];
    }
}

// ---------------- kernel 4: zero h0, c0 -------------------------------------
__global__ void zero_kernel() {
    int i = blockIdx.x * blockDim.x + threadIdx.x;
    if (i < BB * HH) { g_hbuf[0][i] = __float2half(0.f); g_c[i] = 0.f; }
}

// ---------------- kernel 5: fused fp16 GEMM + LSTM step ---------------------
// gates[512,4096] = [w_t | h_{t-1}] (512,1152) @ wcat^T, fused pointwise LSTM.
__global__ __launch_bounds__(256) void fused_step(float* __restrict__ outh, int t) {
    extern __shared__ char smraw[];
    __half* smh = (__half*)smraw;
    float* S = (float*)smraw;
    uint32_t smem_base = smem_u32(smraw);

    const __half* hin = g_hbuf[t & 1];
    __half* hout = g_hbuf[(t + 1) & 1];

    int tid = threadIdx.x;
    int warp = tid >> 5, lane = tid & 31;
    int wm = warp & 1, wn = warp >> 1;   // 2 warps M x 4 warps N
    int bm0 = blockIdx.y * 128, bn0 = blockIdx.x * 128;

    float acc[4][4][4];
#pragma unroll
    for (int i = 0; i < 4; i++)
#pragma unroll
        for (int j = 0; j < 4; j++)
#pragma unroll
            for (int r = 0; r < 4; r++) acc[i][j][r] = 0.f;

    // ---- pipelined loads: each chunk = A(128x32) + B(128x32) halves --------
    auto load_chunk = [&](int c) {
        int s = c & 1;
        int ks = c * 32;
        uint32_t abase = smem_base + s * STAGE_BYTES;
        uint32_t bbase = abase + TILE_HALVES * 2;
#pragma unroll
        for (int i = 0; i < 2; i++) {
            int o = tid + i * 256;       // 0..511
            int r = o >> 2, cc = o & 3;  // row, 16B-chunk within row
            const __half* srcA = (ks < DD)
                ? g_wh + ((size_t)(bm0 + r) * TT + t) * DD + ks + cc * 8
                : hin + (size_t)(bm0 + r) * HH + (ks - DD) + cc * 8;
            cp16(abase + r * (ROW_H * 2) + cc * 16, srcA);
            cp16(bbase + r * (ROW_H * 2) + cc * 16,
                 g_wcat + (size_t)(bn0 + r) * KC + ks + cc * 8);
        }
        cp_commit();
    };

    load_chunk(0);

    for (int c = 0; c < NKT; c++) {
        if (c + 1 < NKT) load_chunk(c + 1);
        if (c + 1 < NKT) cp_wait<1>(); else cp_wait<0>();
        __syncthreads();

        const __half* a = smh + (c & 1) * (STAGE_BYTES / 2);
        const __half* b = a + TILE_HALVES;
#pragma unroll
        for (int kk = 0; kk < 32; kk += 16) {
            int c0 = kk + ((lane & 3) << 1);
            uint32_t af[4][4], bf[4][2];
#pragma unroll
            for (int mt = 0; mt < 4; mt++) {
                int r0 = wm * 64 + mt * 16 + (lane >> 2);
                af[mt][0] = *(const uint32_t*)&a[r0 * ROW_H + c0];
                af[mt][1] = *(const uint32_t*)&a[(r0 + 8) * ROW_H + c0];
                af[mt][2] = *(const uint32_t*)&a[r0 * ROW_H + c0 + 8];
                af[mt][3] = *(const uint32_t*)&a[(r0 + 8) * ROW_H + c0 + 8];
            }
#pragma unroll
            for (int nt = 0; nt < 4; nt++) {
                int n0 = wn * 32 + nt * 8 + (lane >> 2);
                bf[nt][0] = *(const uint32_t*)&b[n0 * ROW_H + c0];
                bf[nt][1] = *(const uint32_t*)&b[n0 * ROW_H + c0 + 8];
            }
#pragma unroll
            for (int mt = 0; mt < 4; mt++)
#pragma unroll
                for (int nt = 0; nt < 4; nt++)
                    asm volatile(
                        "mma.sync.aligned.m16n8k16.row.col.f32.f16.f16.f32 "
                        "{%0,%1,%2,%3}, {%4,%5,%6,%7}, {%8,%9}, {%0,%1,%2,%3};"
                        : "+f"(acc[mt][nt][0]), "+f"(acc[mt][nt][1]),
                          "+f"(acc[mt][nt][2]), "+f"(acc[mt][nt][3])
                        : "r"(af[mt][0]), "r"(af[mt][1]), "r"(af[mt][2]), "r"(af[mt][3]),
                          "r"(bf[nt][0]), "r"(bf[nt][1]));
        }
        __syncthreads();
    }

    // ---- epilogue phase 1: stage gate tile to smem (fp32) ------------------
#pragma unroll
    for (int mt = 0; mt < 4; mt++) {
        int r0 = wm * 64 + mt * 16 + (lane >> 2);
#pragma unroll
        for (int nt = 0; nt < 4; nt++) {
            int c0 = wn * 32 + nt * 8 + ((lane & 3) << 1);
            *(float2*)&S[r0 * EPI_STRIDE + c0] = make_float2(acc[mt][nt][0], acc[mt][nt][1]);
            *(float2*)&S[(r0 + 8) * EPI_STRIDE + c0] = make_float2(acc[mt][nt][2], acc[mt][nt][3]);
        }
    }
    __syncthreads();

    // ---- epilogue phase 2: coalesced LSTM pointwise update -----------------
    {
        float4 bi = *(const float4*)&g_bias[bn0 + 4 * lane];
        int U = (bn0 >> 2) + lane;
#pragma unroll
        for (int i = 0; i < 16; i++) {
            int row = warp * 16 + i;
            float4 g = *(const float4*)&S[row * EPI_STRIDE + 4 * lane];
            int R = bm0 + row;
            size_t ci = (size_t)R * HH + U;
            float cold = g_c[ci];
            float si = sigmoid_fast(g.x + bi.x);
            float sf = sigmoid_fast(g.y + bi.y);
            float gg = tanh_fast(g.z + bi.z);
            float so = sigmoid_fast(g.w + bi.w);
            float cn = sf * cold + si * gg;
            float hn = so * tanh_fast(cn);
            g_c[ci] = cn;
            hout[ci] = __float2half_rn(hn);
            outh[((size_t)R * TT + t) * HH + U] = hn;
        }
    }
}

// ---------------- launch ----------------------------------------------------
extern "C" void kernel_launch(void* const* d_in, const int* in_sizes, int n_in,
                              void* d_out, int out_size) {
    (void)in_sizes; (void)n_in; (void)out_size;
    const float* x     = (const float*)d_in[0];
    const float* wattn = (const float*)d_in[1];
    // d_in[2] = b_attn: irrelevant (softmax shift invariance)
    const float* wih   = (const float*)d_in[3];
    const float* whh   = (const float*)d_in[4];
    const float* bih   = (const float*)d_in[5];
    const float* bhh   = (const float*)d_in[6];

    float* out  = (float*)d_out;
    float* outw = out;                               // (B, T, D)
    float* outh = out + (size_t)BB * TT * DD;        // (B, T, H)

    cudaFuncSetAttribute(fused_step, cudaFuncAttributeMaxDynamicSharedMemorySize, SMEM_BYTES);

    attn_kernel<<<BB, DD>>>(x, wattn);
    weight_kernel<<<2048, 256>>>(x, outw);
    prep_kernel<<<2048, 256>>>(wih, whh, bih, bhh);
    zero_kernel<<<(BB * HH + 255) / 256, 256>>>();

    dim3 grid(32, 4);  // N/128 x M/128
    for (int t = 0; t < TT; t++) {
        fused_step<<<grid, 256, SMEM_BYTES>>>(outh, t);
    }
}

// round 5
// speedup vs baseline: 2.2766x; 1.0256x over previous
#include <cuda_runtime.h>
#include <cuda_fp16.h>
#include <cstdint>
#include <math.h>

#define BB 512
#define TT 255
#define DD 128
#define HH 1024
#define GG 4096   // 4*H
#define KC 1152   // D + H
#define NKT 36    // KC/32

#define NCTA 128      // 64 N-blocks x 2 M-blocks, all co-resident
#define MT 256        // M tile
#define NT 64         // N tile

// smem geometry
#define B_ROW_H 1160                          // 1152 + 8 pad halves (conflict-free)
#define B_BYTES (NT * B_ROW_H * 2)            // 148480
#define A_ROW_H 40                            // 32 + 8 pad halves
#define A_STAGE_BYTES (MT * A_ROW_H * 2)      // 20480
#define STAGES 4
#define SMEM_TOTAL (B_BYTES + STAGES * A_STAGE_BYTES)  // 230400
#define EPI_STRIDE 68                         // fp32 gate staging stride (floats)

// ---------------- scratch (device globals: no allocation allowed) ----------
__device__ __align__(16) float  g_a[BB * DD];
__device__ __align__(16) __half g_wh[(size_t)BB * TT * DD];   // w = a*x fp16
__device__ __align__(16) __half g_hbuf[2][BB * HH];           // h ping-pong fp16
__device__ __align__(16) float  g_c[BB * HH];                 // c state fp32
__device__ __align__(16) __half g_wcat[(size_t)GG * KC];      // permuted weights fp16
__device__ __align__(16) float  g_bias[GG];                   // permuted bias
__device__ unsigned int g_sync;

__device__ __forceinline__ void cp16(uint32_t smem_dst, const void* gmem_src) {
    asm volatile("cp.async.cg.shared.global [%0], [%1], 16;\n" :: "r"(smem_dst), "l"(gmem_src));
}
__device__ __forceinline__ void cp_commit() { asm volatile("cp.async.commit_group;\n"); }
template <int N> __device__ __forceinline__ void cp_wait() {
    asm volatile("cp.async.wait_group %0;\n" :: "n"(N));
}
__device__ __forceinline__ uint32_t smem_u32(const void* p) {
    uint32_t a;
    asm("{ .reg .u64 t; cvta.to.shared.u64 t, %1; cvt.u32.u64 %0, t; }" : "=r"(a) : "l"(p));
    return a;
}
__device__ __forceinline__ float tanh_fast(float x) {
    float y;
    asm("tanh.approx.f32 %0, %1;" : "=f"(y) : "f"(x));
    return y;
}
__device__ __forceinline__ float sigmoid_fast(float x) {
    return __fdividef(1.f, 1.f + __expf(-x));
}
__device__ __forceinline__ unsigned ld_acq(const unsigned* p) {
    unsigned v;
    asm volatile("ld.acquire.gpu.global.u32 %0, [%1];" : "=r"(v) : "l"(p));
    return v;
}

// ---------------- kernel 1: e_x + softmax -> g_a ---------------------------
__global__ void attn_kernel(const float* __restrict__ x, const float* __restrict__ wattn) {
    int b = blockIdx.x, d = threadIdx.x;  // 128 threads
    __shared__ float swx[TT];
    __shared__ float red[8];
    for (int i = d; i < TT; i += DD) swx[i] = wattn[2 * HH + i];
    __syncthreads();
    const float* xb = x + (size_t)b * TT * DD + d;
    float e = 0.f;
#pragma unroll 5
    for (int t = 0; t < TT; t++) e += xb[(size_t)t * DD] * swx[t];
    int lane = d & 31, warp = d >> 5;
    float m = e;
#pragma unroll
    for (int o = 16; o; o >>= 1) m = fmaxf(m, __shfl_xor_sync(0xffffffffu, m, o));
    if (!lane) red[warp] = m;
    __syncthreads();
    m = fmaxf(fmaxf(red[0], red[1]), fmaxf(red[2], red[3]));
    float ex = expf(e - m);
    float s = ex;
#pragma unroll
    for (int o = 16; o; o >>= 1) s += __shfl_xor_sync(0xffffffffu, s, o);
    if (!lane) red[4 + warp] = s;
    __syncthreads();
    s = red[4] + red[5] + red[6] + red[7];
    g_a[b * DD + d] = ex / s;
}

// ---------------- kernel 2: w = a*x -> outw (fp32) + g_wh (fp16) -----------
__global__ void weight_kernel(const float* __restrict__ x, float* __restrict__ outw) {
    size_t n4 = (size_t)BB * TT * DD / 4;
    const float4* x4 = (const float4*)x;
    const float4* a4 = (const float4*)g_a;
    float4* o4 = (float4*)outw;
    __half2* h2 = (__half2*)g_wh;
    for (size_t i = (size_t)blockIdx.x * blockDim.x + threadIdx.x; i < n4;
         i += (size_t)gridDim.x * blockDim.x) {
        size_t b = i / (TT * 32);
        int d4 = (int)(i % 32);
        float4 av = a4[b * 32 + d4];
        float4 xv = x4[i];
        float4 w = make_float4(av.x * xv.x, av.y * xv.y, av.z * xv.z, av.w * xv.w);
        o4[i] = w;
        h2[2 * i]     = __floats2half2_rn(w.x, w.y);
        h2[2 * i + 1] = __floats2half2_rn(w.z, w.w);
    }
}

// ---------------- kernel 3: permuted fp16 weights + bias --------------------
// output col n <-> gate row r = (n&3)*H + (n>>2): 4-col groups = (i,f,g,o) quads
__global__ void prep_kernel(const float* __restrict__ wih, const float* __restrict__ whh,
                            const float* __restrict__ bih, const float* __restrict__ bhh) {
    size_t n = (size_t)GG * KC;
    size_t tid0 = (size_t)blockIdx.x * blockDim.x + threadIdx.x;
    for (size_t i = tid0; i < n; i += (size_t)gridDim.x * blockDim.x) {
        int k = (int)(i % KC);
        int nn = (int)(i / KC);
        int r = (nn & 3) * HH + (nn >> 2);
        float v = (k < DD) ? wih[(size_t)r * DD + k] : whh[(size_t)r * HH + (k - DD)];
        g_wcat[i] = __float2half_rn(v);
    }
    if (tid0 < GG) {
        int r = ((int)tid0 & 3) * HH + ((int)tid0 >> 2);
        g_bias[tid0] = bih[r] + bhh[r];
    }
}

// ---------------- kernel 4: zero h0, c0, sync counter -----------------------
__global__ void zero_kernel() {
    int i = blockIdx.x * blockDim.x + threadIdx.x;
    if (i < BB * HH) { g_hbuf[0][i] = __float2half(0.f); g_c[i] = 0.f; }
    if (i == 0) g_sync = 0;
}

// ---------------- kernel 5: persistent fused LSTM ---------------------------
// 128 CTAs resident; each owns a (MT=256, NT=64) tile; B slab stays in SMEM
// for all 255 steps; grid-wide barrier between steps.
__global__ __launch_bounds__(256) void persistent_lstm(float* __restrict__ outh) {
    extern __shared__ char smraw[];
    __half* smB = (__half*)smraw;
    __half* smA = (__half*)(smraw + B_BYTES);
    float* S = (float*)(smraw + B_BYTES);          // epilogue staging (reuses A region)
    uint32_t smem_base = smem_u32(smraw);
    uint32_t a_base = smem_base + B_BYTES;

    int tid = threadIdx.x;
    int warp = tid >> 5, lane = tid & 31;
    int wn = warp & 1, wm = warp >> 1;             // 2 warps N x 4 warps M
    int bx = blockIdx.x;
    int mb = bx >> 6, nb = bx & 63;
    int bm0 = mb * MT, bn0 = nb * NT;

    // ---- load resident B slab: 64 x 1152 halves (one group) ----------------
    for (int i = tid; i < NT * (KC / 8); i += 256) {
        int n = i / (KC / 8), kc = i % (KC / 8);
        cp16(smem_base + n * (B_ROW_H * 2) + kc * 16,
             g_wcat + (size_t)(bn0 + n) * KC + kc * 8);
    }
    cp_commit();

    for (int t = 0; t < TT; t++) {
        const __half* hin = g_hbuf[t & 1];
        __half* hout = g_hbuf[(t + 1) & 1];

        float acc[4][4][4];
#pragma unroll
        for (int i = 0; i < 4; i++)
#pragma unroll
            for (int j = 0; j < 4; j++)
#pragma unroll
                for (int r = 0; r < 4; r++) acc[i][j][r] = 0.f;

        // A chunk loader: 256x32 halves into stage c%4
        auto load_chunk = [&](int c) {
            int ks = c * 32;
            uint32_t ab = a_base + (c & 3) * A_STAGE_BYTES;
#pragma unroll
            for (int i = 0; i < 4; i++) {
                int o = tid + i * 256;       // 0..1023
                int r = o >> 2, cc = o & 3;
                const __half* src = (ks < DD)
                    ? g_wh + ((size_t)(bm0 + r) * TT + t) * DD + ks + cc * 8
                    : hin + (size_t)(bm0 + r) * HH + (ks - DD) + cc * 8;
                cp16(ab + r * (A_ROW_H * 2) + cc * 16, src);
            }
            cp_commit();
        };

        load_chunk(0); load_chunk(1); load_chunk(2);

        for (int c = 0; c < NKT; c++) {
            int rem = NKT - 1 - c;
            if (rem >= 2)      cp_wait<2>();
            else if (rem == 1) cp_wait<1>();
            else               cp_wait<0>();
            __syncthreads();
            // issue next stage AFTER the sync: all warps are past compute(c-1),
            // so overwriting buffer (c+3)&3 == (c-1)&3 is safe.
            if (c + 3 < NKT) load_chunk(c + 3);

            const __half* a = smA + (c & 3) * (A_STAGE_BYTES / 2);
#pragma unroll
            for (int kk = 0; kk < 32; kk += 16) {
                int c0 = kk + ((lane & 3) << 1);
                uint32_t af[4][4], bf[4][2];
#pragma unroll
                for (int mt = 0; mt < 4; mt++) {
                    int r0 = wm * 64 + mt * 16 + (lane >> 2);
                    af[mt][0] = *(const uint32_t*)&a[r0 * A_ROW_H + c0];
                    af[mt][1] = *(const uint32_t*)&a[(r0 + 8) * A_ROW_H + c0];
                    af[mt][2] = *(const uint32_t*)&a[r0 * A_ROW_H + c0 + 8];
                    af[mt][3] = *(const uint32_t*)&a[(r0 + 8) * A_ROW_H + c0 + 8];
                }
                int bcol = c * 32 + c0;
#pragma unroll
                for (int nt = 0; nt < 4; nt++) {
                    int n0 = wn * 32 + nt * 8 + (lane >> 2);
                    bf[nt][0] = *(const uint32_t*)&smB[n0 * B_ROW_H + bcol];
                    bf[nt][1] = *(const uint32_t*)&smB[n0 * B_ROW_H + bcol + 8];
                }
#pragma unroll
                for (int mt = 0; mt < 4; mt++)
#pragma unroll
                    for (int nt = 0; nt < 4; nt++)
                        asm volatile(
                            "mma.sync.aligned.m16n8k16.row.col.f32.f16.f16.f32 "
                            "{%0,%1,%2,%3}, {%4,%5,%6,%7}, {%8,%9}, {%0,%1,%2,%3};"
                            : "+f"(acc[mt][nt][0]), "+f"(acc[mt][nt][1]),
                              "+f"(acc[mt][nt][2]), "+f"(acc[mt][nt][3])
                            : "r"(af[mt][0]), "r"(af[mt][1]), "r"(af[mt][2]), "r"(af[mt][3]),
                              "r"(bf[nt][0]), "r"(bf[nt][1]));
            }
        }
        __syncthreads();  // all MMA fragment reads done; A region reusable as S

        // ---- epilogue phase 1: stage gates to smem (fp32) -------------------
#pragma unroll
        for (int mt = 0; mt < 4; mt++) {
            int r0 = wm * 64 + mt * 16 + (lane >> 2);
#pragma unroll
            for (int nt = 0; nt < 4; nt++) {
                int c0 = wn * 32 + nt * 8 + ((lane & 3) << 1);
                *(float2*)&S[r0 * EPI_STRIDE + c0] =
                    make_float2(acc[mt][nt][0], acc[mt][nt][1]);
                *(float2*)&S[(r0 + 8) * EPI_STRIDE + c0] =
                    make_float2(acc[mt][nt][2], acc[mt][nt][3]);
            }
        }
        __syncthreads();

        // ---- epilogue phase 2: coalesced LSTM update ------------------------
        {
            int u = tid & 15;
            int U = nb * 16 + u;
            float4 bi = *(const float4*)&g_bias[bn0 + 4 * u];
#pragma unroll
            for (int i = 0; i < 16; i++) {
                int row = (tid >> 4) + i * 16;
                float4 g = *(const float4*)&S[row * EPI_STRIDE + 4 * u];
                int R = bm0 + row;
                size_t ci = (size_t)R * HH + U;
                float cold = g_c[ci];
                float si = sigmoid_fast(g.x + bi.x);
                float sf = sigmoid_fast(g.y + bi.y);
                float gg = tanh_fast(g.z + bi.z);
                float so = sigmoid_fast(g.w + bi.w);
                float cn = sf * cold + si * gg;
                float hn = so * tanh_fast(cn);
                g_c[ci] = cn;
                hout[ci] = __float2half_rn(hn);
                outh[((size_t)R * TT + t) * HH + U] = hn;
            }
        }

        // ---- grid-wide step barrier -----------------------------------------
        if (t + 1 < TT) {
            __threadfence();
            __syncthreads();
            if (tid == 0) {
                atomicAdd(&g_sync, 1u);
                unsigned tgt = (unsigned)NCTA * (unsigned)(t + 1);
                while (ld_acq(&g_sync) < tgt) {}
            }
            __syncthreads();
        }
    }
}

// ---------------- launch ----------------------------------------------------
extern "C" void kernel_launch(void* const* d_in, const int* in_sizes, int n_in,
                              void* d_out, int out_size) {
    (void)in_sizes; (void)n_in; (void)out_size;
    const float* x     = (const float*)d_in[0];
    const float* wattn = (const float*)d_in[1];
    // d_in[2] = b_attn: irrelevant (softmax shift invariance)
    const float* wih   = (const float*)d_in[3];
    const float* whh   = (const float*)d_in[4];
    const float* bih   = (const float*)d_in[5];
    const float* bhh   = (const float*)d_in[6];

    float* out  = (float*)d_out;
    float* outw = out;                               // (B, T, D)
    float* outh = out + (size_t)BB * TT * DD;        // (B, T, H)

    cudaFuncSetAttribute(persistent_lstm, cudaFuncAttributeMaxDynamicSharedMemorySize,
                         SMEM_TOTAL);

    attn_kernel<<<BB, DD>>>(x, wattn);
    weight_kernel<<<2048, 256>>>(x, outw);
    prep_kernel<<<2048, 256>>>(wih, whh, bih, bhh);
    zero_kernel<<<(BB * HH + 255) / 256, 256>>>();

    persistent_lstm<<<NCTA, 256, SMEM_TOTAL>>>(outh);
}

// round 6
// speedup vs baseline: 2.4547x; 1.0782x over previous
#include <cuda_runtime.h>
#include <cuda_fp16.h>
#include <cstdint>
#include <math.h>

#define BB 512
#define TT 255
#define DD 128
#define HH 1024
#define GG 4096   // 4*H
#define KC 1152   // D + H
#define NKT 36    // KC/32

#define NCTA 128      // 64 N-blocks x 2 M-blocks, all co-resident
#define MT 256        // M tile
#define NT 64         // N tile

// smem geometry
#define B_ROW_H 1160                          // 1152 + 8 pad halves (conflict-free)
#define B_BYTES (NT * B_ROW_H * 2)            // 148480
#define A_ROW_H 40                            // 32 + 8 pad halves
#define A_STAGE_BYTES (MT * A_ROW_H * 2)      // 20480
#define STAGES 4
#define SMEM_TOTAL (B_BYTES + STAGES * A_STAGE_BYTES)  // 230400
#define EPI_STRIDE 68                         // fp32 gate staging stride (floats)

// ---------------- scratch (device globals: no allocation allowed) ----------
__device__ __align__(16) float  g_a[BB * DD];
__device__ __align__(16) __half g_wh[(size_t)BB * TT * DD];   // w = a*x fp16
__device__ __align__(16) __half g_hbuf[2][BB * HH];           // h ping-pong fp16
__device__ __align__(16) float  g_c[BB * HH];                 // c state fp32
__device__ __align__(16) __half g_wcat[(size_t)GG * KC];      // permuted weights fp16
__device__ __align__(16) float  g_bias[GG];                   // permuted bias
__device__ unsigned int g_sync[2];

__device__ __forceinline__ void cp16(uint32_t smem_dst, const void* gmem_src) {
    asm volatile("cp.async.cg.shared.global [%0], [%1], 16;\n" :: "r"(smem_dst), "l"(gmem_src));
}
__device__ __forceinline__ void cp_commit() { asm volatile("cp.async.commit_group;\n"); }
template <int N> __device__ __forceinline__ void cp_wait() {
    asm volatile("cp.async.wait_group %0;\n" :: "n"(N));
}
__device__ __forceinline__ uint32_t smem_u32(const void* p) {
    uint32_t a;
    asm("{ .reg .u64 t; cvta.to.shared.u64 t, %1; cvt.u32.u64 %0, t; }" : "=r"(a) : "l"(p));
    return a;
}
__device__ __forceinline__ void ldsm4(uint32_t& r0, uint32_t& r1, uint32_t& r2, uint32_t& r3,
                                      uint32_t addr) {
    asm volatile("ldmatrix.sync.aligned.m8n8.x4.shared.b16 {%0,%1,%2,%3}, [%4];"
                 : "=r"(r0), "=r"(r1), "=r"(r2), "=r"(r3) : "r"(addr));
}
__device__ __forceinline__ float tanh_fast(float x) {
    float y;
    asm("tanh.approx.f32 %0, %1;" : "=f"(y) : "f"(x));
    return y;
}
__device__ __forceinline__ float sigmoid_fast(float x) {
    return __fdividef(1.f, 1.f + __expf(-x));
}
__device__ __forceinline__ unsigned ld_acq(const unsigned* p) {
    unsigned v;
    asm volatile("ld.acquire.gpu.global.u32 %0, [%1];" : "=r"(v) : "l"(p));
    return v;
}

// ---------------- kernel 1: e_x + softmax -> g_a ---------------------------
__global__ void attn_kernel(const float* __restrict__ x, const float* __restrict__ wattn) {
    int b = blockIdx.x, d = threadIdx.x;  // 128 threads
    __shared__ float swx[TT];
    __shared__ float red[8];
    for (int i = d; i < TT; i += DD) swx[i] = wattn[2 * HH + i];
    __syncthreads();
    const float* xb = x + (size_t)b * TT * DD + d;
    float e = 0.f;
#pragma unroll 5
    for (int t = 0; t < TT; t++) e += xb[(size_t)t * DD] * swx[t];
    int lane = d & 31, warp = d >> 5;
    float m = e;
#pragma unroll
    for (int o = 16; o; o >>= 1) m = fmaxf(m, __shfl_xor_sync(0xffffffffu, m, o));
    if (!lane) red[warp] = m;
    __syncthreads();
    m = fmaxf(fmaxf(red[0], red[1]), fmaxf(red[2], red[3]));
    float ex = expf(e - m);
    float s = ex;
#pragma unroll
    for (int o = 16; o; o >>= 1) s += __shfl_xor_sync(0xffffffffu, s, o);
    if (!lane) red[4 + warp] = s;
    __syncthreads();
    s = red[4] + red[5] + red[6] + red[7];
    g_a[b * DD + d] = ex / s;
}

// ---------------- kernel 2: w = a*x -> outw (fp32) + g_wh (fp16) -----------
__global__ void weight_kernel(const float* __restrict__ x, float* __restrict__ outw) {
    size_t n4 = (size_t)BB * TT * DD / 4;
    const float4* x4 = (const float4*)x;
    const float4* a4 = (const float4*)g_a;
    float4* o4 = (float4*)outw;
    __half2* h2 = (__half2*)g_wh;
    for (size_t i = (size_t)blockIdx.x * blockDim.x + threadIdx.x; i < n4;
         i += (size_t)gridDim.x * blockDim.x) {
        size_t b = i / (TT * 32);
        int d4 = (int)(i % 32);
        float4 av = a4[b * 32 + d4];
        float4 xv = x4[i];
        float4 w = make_float4(av.x * xv.x, av.y * xv.y, av.z * xv.z, av.w * xv.w);
        o4[i] = w;
        h2[2 * i]     = __floats2half2_rn(w.x, w.y);
        h2[2 * i + 1] = __floats2half2_rn(w.z, w.w);
    }
}

// ---------------- kernel 3: permuted fp16 weights + bias --------------------
// output col n <-> gate row r = (n&3)*H + (n>>2): 4-col groups = (i,f,g,o) quads
__global__ void prep_kernel(const float* __restrict__ wih, const float* __restrict__ whh,
                            const float* __restrict__ bih, const float* __restrict__ bhh) {
    size_t n = (size_t)GG * KC;
    size_t tid0 = (size_t)blockIdx.x * blockDim.x + threadIdx.x;
    for (size_t i = tid0; i < n; i += (size_t)gridDim.x * blockDim.x) {
        int k = (int)(i % KC);
        int nn = (int)(i / KC);
        int r = (nn & 3) * HH + (nn >> 2);
        float v = (k < DD) ? wih[(size_t)r * DD + k] : whh[(size_t)r * HH + (k - DD)];
        g_wcat[i] = __float2half_rn(v);
    }
    if (tid0 < GG) {
        int r = ((int)tid0 & 3) * HH + ((int)tid0 >> 2);
        g_bias[tid0] = bih[r] + bhh[r];
    }
}

// ---------------- kernel 4: zero h0, c0, sync counters ----------------------
__global__ void zero_kernel() {
    int i = blockIdx.x * blockDim.x + threadIdx.x;
    if (i < BB * HH) { g_hbuf[0][i] = __float2half(0.f); g_c[i] = 0.f; }
    if (i < 2) g_sync[i] = 0;
}

// ---------------- kernel 5: persistent fused LSTM ---------------------------
// 128 CTAs resident; each owns a (MT=256, NT=64) tile; B slab stays in SMEM
// for all 255 steps; per-M-group grid barrier between steps; ldmatrix frags.
__global__ __launch_bounds__(256) void persistent_lstm(float* __restrict__ outh) {
    extern __shared__ char smraw[];
    float* S = (float*)(smraw + B_BYTES);          // epilogue staging (A region reuse)
    uint32_t smem_base = smem_u32(smraw);
    uint32_t a_base = smem_base + B_BYTES;

    int tid = threadIdx.x;
    int warp = tid >> 5, lane = tid & 31;
    int wn = warp & 1, wm = warp >> 1;             // 2 warps N x 4 warps M
    int bx = blockIdx.x;
    int mb = bx >> 6, nb = bx & 63;
    int bm0 = mb * MT, bn0 = nb * NT;

    // ---- load resident B slab: 64 x 1152 halves -----------------------------
    for (int i = tid; i < NT * (KC / 8); i += 256) {
        int n = i / (KC / 8), kc = i % (KC / 8);
        cp16(smem_base + n * (B_ROW_H * 2) + kc * 16,
             g_wcat + (size_t)(bn0 + n) * KC + kc * 8);
    }
    cp_commit();

    // ---- per-thread ldmatrix lane offsets (bytes), computed once ------------
    // A x4: g=lane>>3 -> (row += (g&1)*8, col += (g>>1)*8)
    int arow = (lane & 7) + ((lane >> 3) & 1) * 8;
    int acol = ((lane >> 4) & 1) * 8;
    uint32_t a_lane_off = (uint32_t)(((wm * 64 + arow) * A_ROW_H + acol) * 2);
    // B x4: g=lane>>3 -> (col += (g&1)*8, row += (g>>1)*8)
    int brow = (lane & 7) + ((lane >> 4) & 1) * 8;
    int bcol = ((lane >> 3) & 1) * 8;
    uint32_t b_lane_base = smem_base + (uint32_t)(((wn * 32 + brow) * B_ROW_H + bcol) * 2);

    for (int t = 0; t < TT; t++) {
        const __half* hin = g_hbuf[t & 1];
        __half* hout = g_hbuf[(t + 1) & 1];

        float acc[4][4][4];
#pragma unroll
        for (int i = 0; i < 4; i++)
#pragma unroll
            for (int j = 0; j < 4; j++)
#pragma unroll
                for (int r = 0; r < 4; r++) acc[i][j][r] = 0.f;

        // A chunk loader: 256x32 halves into stage c%4
        auto load_chunk = [&](int c) {
            int ks = c * 32;
            uint32_t ab = a_base + (c & 3) * A_STAGE_BYTES;
#pragma unroll
            for (int i = 0; i < 4; i++) {
                int o = tid + i * 256;       // 0..1023
                int r = o >> 2, cc = o & 3;
                const __half* src = (ks < DD)
                    ? g_wh + ((size_t)(bm0 + r) * TT + t) * DD + ks + cc * 8
                    : hin + (size_t)(bm0 + r) * HH + (ks - DD) + cc * 8;
                cp16(ab + r * (A_ROW_H * 2) + cc * 16, src);
            }
            cp_commit();
        };

        load_chunk(0); load_chunk(1); load_chunk(2);

        for (int c = 0; c < NKT; c++) {
            int rem = NKT - 1 - c;
            if (rem >= 2)      cp_wait<2>();
            else if (rem == 1) cp_wait<1>();
            else               cp_wait<0>();
            __syncthreads();
            // issue next stage AFTER the sync: all warps are past compute(c-1),
            // so overwriting buffer (c+3)&3 == (c-1)&3 is safe.
            if (c + 3 < NKT) load_chunk(c + 3);

            uint32_t ab = a_base + (c & 3) * A_STAGE_BYTES + a_lane_off;
            uint32_t bb = b_lane_base + c * 64;   // 32 cols * 2B per chunk
#pragma unroll
            for (int kk = 0; kk < 2; kk++) {
                uint32_t af[4][4], bf[4][2];
#pragma unroll
                for (int mt = 0; mt < 4; mt++)
                    ldsm4(af[mt][0], af[mt][1], af[mt][2], af[mt][3],
                          ab + mt * (16 * A_ROW_H * 2) + kk * 32);
#pragma unroll
                for (int p = 0; p < 2; p++)
                    ldsm4(bf[2 * p][0], bf[2 * p][1], bf[2 * p + 1][0], bf[2 * p + 1][1],
                          bb + p * (16 * B_ROW_H * 2) + kk * 32);
#pragma unroll
                for (int mt = 0; mt < 4; mt++)
#pragma unroll
                    for (int nt = 0; nt < 4; nt++)
                        asm volatile(
                            "mma.sync.aligned.m16n8k16.row.col.f32.f16.f16.f32 "
                            "{%0,%1,%2,%3}, {%4,%5,%6,%7}, {%8,%9}, {%0,%1,%2,%3};"
                            : "+f"(acc[mt][nt][0]), "+f"(acc[mt][nt][1]),
                              "+f"(acc[mt][nt][2]), "+f"(acc[mt][nt][3])
                            : "r"(af[mt][0]), "r"(af[mt][1]), "r"(af[mt][2]), "r"(af[mt][3]),
                              "r"(bf[nt][0]), "r"(bf[nt][1]));
            }
        }
        __syncthreads();  // all MMA fragment reads done; A region reusable as S

        // ---- epilogue phase 1: stage gates to smem (fp32) -------------------
#pragma unroll
        for (int mt = 0; mt < 4; mt++) {
            int r0 = wm * 64 + mt * 16 + (lane >> 2);
#pragma unroll
            for (int nt = 0; nt < 4; nt++) {
                int c0 = wn * 32 + nt * 8 + ((lane & 3) << 1);
                *(float2*)&S[r0 * EPI_STRIDE + c0] =
                    make_float2(acc[mt][nt][0], acc[mt][nt][1]);
                *(float2*)&S[(r0 + 8) * EPI_STRIDE + c0] =
                    make_float2(acc[mt][nt][2], acc[mt][nt][3]);
            }
        }
        __syncthreads();

        // ---- epilogue phase 2: coalesced LSTM update ------------------------
        {
            int u = tid & 15;
            int U = nb * 16 + u;
            float4 bi = *(const float4*)&g_bias[bn0 + 4 * u];
#pragma unroll
            for (int i = 0; i < 16; i++) {
                int row = (tid >> 4) + i * 16;
                float4 g = *(const float4*)&S[row * EPI_STRIDE + 4 * u];
                int R = bm0 + row;
                size_t ci = (size_t)R * HH + U;
                float cold = g_c[ci];
                float si = sigmoid_fast(g.x + bi.x);
                float sf = sigmoid_fast(g.y + bi.y);
                float gg = tanh_fast(g.z + bi.z);
                float so = sigmoid_fast(g.w + bi.w);
                float cn = sf * cold + si * gg;
                float hn = so * tanh_fast(cn);
                g_c[ci] = cn;
                hout[ci] = __float2half_rn(hn);
                outh[((size_t)R * TT + t) * HH + U] = hn;
            }
        }

        // ---- per-M-group grid barrier (64 CTAs each) -------------------------
        if (t + 1 < TT) {
            __threadfence();
            __syncthreads();
            if (tid == 0) {
                atomicAdd(&g_sync[mb], 1u);
                unsigned tgt = 64u * (unsigned)(t + 1);
                while (ld_acq(&g_sync[mb]) < tgt) {}
            }
            __syncthreads();
        }
    }
}

// ---------------- launch ----------------------------------------------------
extern "C" void kernel_launch(void* const* d_in, const int* in_sizes, int n_in,
                              void* d_out, int out_size) {
    (void)in_sizes; (void)n_in; (void)out_size;
    const float* x     = (const float*)d_in[0];
    const float* wattn = (const float*)d_in[1];
    // d_in[2] = b_attn: irrelevant (softmax shift invariance)
    const float* wih   = (const float*)d_in[3];
    const float* whh   = (const float*)d_in[4];
    const float* bih   = (const float*)d_in[5];
    const float* bhh   = (const float*)d_in[6];

    float* out  = (float*)d_out;
    float* outw = out;                               // (B, T, D)
    float* outh = out + (size_t)BB * TT * DD;        // (B, T, H)

    cudaFuncSetAttribute(persistent_lstm, cudaFuncAttributeMaxDynamicSharedMemorySize,
                         SMEM_TOTAL);

    attn_kernel<<<BB, DD>>>(x, wattn);
    weight_kernel<<<2048, 256>>>(x, outw);
    prep_kernel<<<2048, 256>>>(wih, whh, bih, bhh);
    zero_kernel<<<(BB * HH + 255) / 256, 256>>>();

    persistent_lstm<<<NCTA, 256, SMEM_TOTAL>>>(outh);
}